// round 12
// baseline (speedup 1.0000x reference)
#include <cuda_runtime.h>

// DynamicConv2d: B=64, C=8, H=W=256, OUT_C=8, K=3, pad=1.
// R11: fat threads (1 col x 4 rows x 8 och) + DUPLICATED-SPLAT smem tile:
//      every input float stored as (v,v) so splats are direct LDS.64 (no
//      movs); weights read as double2 (LDS.128, 2 och-pairs per load).
//      Per c: 18 LDS.128(w) + 18 LDS.64(in) + 144 FFMA2 => 80% FFMA2 mix.
//      TY=4 tile, 51.7KB smem, __launch_bounds__(128,3).

typedef unsigned long long u64;

#define TY 4                     // output rows per tile
#define NR 6                     // input rows per tile (4 + 2 halo)
#define DST 264                  // dup row stride (floats); col g at 2g+4
#define CH_D (NR * DST)          // 1584 floats per channel
#define SMEM_W 576               // packed weights: 72*8
#define SMEM_FLOATS (SMEM_W + 8 * CH_D)   // 13248
#define SMEM_BYTES (SMEM_FLOATS * 4)      // 52992

// Packed weight scratch: [b][c*9+kk][o], o fastest => och pairs 8B-aligned,
// 4 pairs per tap are 32 contiguous bytes (2x LDS.128).
__device__ __align__(16) float g_wpack[64 * 72 * 8];

__global__ void gen_weights_kernel(const float* __restrict__ dw,
                                   const float* __restrict__ Wg,
                                   const float* __restrict__ bg) {
    int b = blockIdx.x;
    int t = threadIdx.x;          // 0..575
    int j = t >> 3;               // c*9 + kk
    int o = t & 7;                // output channel (torch .view quirk)
    const float* dwp = dw + (b * 8 + o) * 8;
    const float* wgp = Wg + j * 8;
    float v = bg[j];
#pragma unroll
    for (int i = 0; i < 8; i++) v = fmaf(dwp[i], wgp[i], v);
    g_wpack[(b * 72 + j) * 8 + o] = v;
}

__global__ __launch_bounds__(128, 3)
void conv_kernel(const float* __restrict__ x, float* __restrict__ out) {
    extern __shared__ float sm[];
    float* sw  = sm;               // 576 floats packed weights
    float* sin = sm + SMEM_W;      // duplicated tile: col g at idx 2g+4

    int bi = blockIdx.x;
    int b  = bi >> 7;              // batch
    int y0 = ((bi >> 1) & 63) * TY;
    int x0 = (bi & 1) * 128;
    int tx = threadIdx.x;          // column within tile 0..127

    // --- weights: 576 floats = 144 float4 ---
    {
        const float4* wsrc = (const float4*)(g_wpack + b * 576);
        ((float4*)sw)[tx] = wsrc[tx];
        if (tx < 16) ((float4*)sw)[tx + 128] = wsrc[tx + 128];
    }

    // --- input tile: LDG.128 -> duplicated STS.128 x2 ---
    const float* xb = x + (size_t)b * (8 * 65536);
    {
#pragma unroll
        for (int k = 0; k < 12; k++) {       // 48 rows x 32 quads / 128 thr
            int i = tx + 128 * k;
            int row = i >> 5;                // 0..47 = c*6 + t
            int q   = i & 31;
            int c = row / 6;
            int t = row - 6 * c;
            int gy = y0 - 1 + t;
            float4 v = make_float4(0.f, 0.f, 0.f, 0.f);
            if ((unsigned)gy < 256u)
                v = *(const float4*)(xb + c * 65536 + gy * 256 + x0 + 4 * q);
            float* d = sin + c * CH_D + t * DST + 8 * q + 4;   // 16B aligned
            ((float4*)d)[0] = make_float4(v.x, v.x, v.y, v.y);
            ((float4*)d)[1] = make_float4(v.z, v.z, v.w, v.w);
        }
        // halo: left col -1 -> idx 2, right col 128 -> idx 260 (dup float2)
        if (tx < 96) {
            int side = tx >= 48;
            int rr = side ? tx - 48 : tx;    // 0..47
            int c = rr / 6;
            int t = rr - 6 * c;
            int gy = y0 - 1 + t;
            int gx = side ? (x0 + 128) : (x0 - 1);
            float v = 0.f;
            if (((unsigned)gy < 256u) && ((unsigned)gx < 256u))
                v = __ldg(xb + c * 65536 + gy * 256 + gx);
            *(float2*)(sin + c * CH_D + t * DST + (side ? 260 : 2)) =
                make_float2(v, v);
        }
    }
    __syncthreads();

    // --- accumulate: acc[r][q] packs och (2q, 2q+1) for this column ---
    u64 acc[TY][4];
#pragma unroll
    for (int r = 0; r < TY; r++)
#pragma unroll
        for (int q = 0; q < 4; q++) acc[r][q] = 0ull;

    const double2* swd = (const double2*)sw;

#pragma unroll 1
    for (int c = 0; c < 8; c++) {
        // 36 natural och-pairs for all 8 och: 2 LDS.128 per tap
        u64 w[9][4];
#pragma unroll
        for (int kk = 0; kk < 9; kk++) {
            double2 A = swd[(c * 9 + kk) * 2 + 0];
            double2 B = swd[(c * 9 + kk) * 2 + 1];
            w[kk][0] = __double_as_longlong(A.x);
            w[kk][1] = __double_as_longlong(A.y);
            w[kk][2] = __double_as_longlong(B.x);
            w[kk][3] = __double_as_longlong(B.y);
        }
        const float* sc = sin + c * CH_D + 2 * tx;
#pragma unroll
        for (int t = 0; t < NR; t++) {
            const float* rp = sc + t * DST;
            u64 d0 = *(const u64*)(rp + 2);  // (v[cx-1], v[cx-1])
            u64 d1 = *(const u64*)(rp + 4);  // (v[cx  ], v[cx  ])
            u64 d2 = *(const u64*)(rp + 6);  // (v[cx+1], v[cx+1])
#pragma unroll
            for (int kh = 0; kh < 3; kh++) {
                int r = t - kh;              // output row this tap feeds
                if (r >= 0 && r < TY) {
#pragma unroll
                    for (int q = 0; q < 4; q++) {
                        asm("fma.rn.f32x2 %0, %1, %2, %0;"
                            : "+l"(acc[r][q]) : "l"(d0), "l"(w[kh * 3 + 0][q]));
                        asm("fma.rn.f32x2 %0, %1, %2, %0;"
                            : "+l"(acc[r][q]) : "l"(d1), "l"(w[kh * 3 + 1][q]));
                        asm("fma.rn.f32x2 %0, %1, %2, %0;"
                            : "+l"(acc[r][q]) : "l"(d2), "l"(w[kh * 3 + 2][q]));
                    }
                }
            }
        }
    }

    // --- write out: acc[r][q] = (och 2q, och 2q+1), scalar STG each ---
    float* ob = out + (size_t)b * (8 * 65536) + x0;
#pragma unroll
    for (int r = 0; r < TY; r++) {
#pragma unroll
        for (int q = 0; q < 4; q++) {
            unsigned lo, hi;
            asm("mov.b64 {%0, %1}, %2;" : "=r"(lo), "=r"(hi) : "l"(acc[r][q]));
            ob[(2 * q + 0) * 65536 + (y0 + r) * 256 + tx] = __uint_as_float(lo);
            ob[(2 * q + 1) * 65536 + (y0 + r) * 256 + tx] = __uint_as_float(hi);
        }
    }
}

extern "C" void kernel_launch(void* const* d_in, const int* in_sizes, int n_in,
                              void* d_out, int out_size) {
    const float* x  = (const float*)d_in[0];
    const float* dw = (const float*)d_in[1];
    const float* Wg = (const float*)d_in[2];
    const float* bg = (const float*)d_in[3];
    float* out = (float*)d_out;

    cudaFuncSetAttribute(conv_kernel, cudaFuncAttributeMaxDynamicSharedMemorySize,
                         SMEM_BYTES);

    gen_weights_kernel<<<64, 576>>>(dw, Wg, bg);

    conv_kernel<<<64 * 2 * 64, 128, SMEM_BYTES>>>(x, out);
}

// round 15
// speedup vs baseline: 1.2003x; 1.2003x over previous
#include <cuda_runtime.h>

// DynamicConv2d: B=64, C=8, H=W=256, OUT_C=8, K=3, pad=1.
// R12: R10 (best: fat threads, 1 col x 8 rows x 8 och, single-copy tile,
//      och-pair f32x2) + two safe deltas:
//      (1) weight loads as double2 LDS.128 (18/c instead of 36, broadcast,
//          register-pair aliasing => zero movs),
//      (2) weight generation INLINED into the conv CTA (gen kernel and
//          g_wpack round-trip removed; Wg is L2-resident, 2.3KB).

typedef unsigned long long u64;

#define TY 8                    // output rows per tile
#define TX 128                  // output cols per tile
#define SIN_STRIDE 136          // row stride (floats); col g stored at g+4
#define SIN_ROWS (TY + 2)       // 10
#define SIN_PER_C (SIN_ROWS * SIN_STRIDE)     // 1360
#define SMEM_W 576              // packed weights: 72*8, o fastest
#define SMEM_FLOATS (SMEM_W + 8 * SIN_PER_C)  // 11456
#define SMEM_BYTES (SMEM_FLOATS * 4)          // 45824

__global__ __launch_bounds__(128, 3)
void conv_kernel(const float* __restrict__ x,
                 const float* __restrict__ dwg,
                 const float* __restrict__ Wg,
                 const float* __restrict__ bg,
                 float* __restrict__ out) {
    extern __shared__ float sm[];
    float* sw  = sm;               // 576 floats packed weights [j][o]
    float* sin = sm + SMEM_W;      // 8 ch x 10 rows x 136; col g at g+4

    int bi = blockIdx.x;
    int b  = bi >> 6;              // batch
    int y0 = ((bi >> 1) & 31) * TY;
    int x0 = (bi & 1) * TX;
    int tx = threadIdx.x;          // column within tile 0..127

    // --- inline weight generation: sw[j*8+o] = bg[j] + dwg[b][o] . Wg[j] ---
    {
#pragma unroll
        for (int i0 = 0; i0 < 576; i0 += 128) {
            int i = i0 + tx;
            if (i < 576) {
                int j = i >> 3;          // c*9 + kk
                int o = i & 7;           // output channel (torch .view quirk)
                const float4* dwp = (const float4*)(dwg + (b * 8 + o) * 8);
                const float4* wgp = (const float4*)(Wg + j * 8);
                float4 a0 = dwp[0], a1 = dwp[1];
                float4 w0 = wgp[0], w1 = wgp[1];
                float v = bg[j];
                v = fmaf(a0.x, w0.x, v); v = fmaf(a0.y, w0.y, v);
                v = fmaf(a0.z, w0.z, v); v = fmaf(a0.w, w0.w, v);
                v = fmaf(a1.x, w1.x, v); v = fmaf(a1.y, w1.y, v);
                v = fmaf(a1.z, w1.z, v); v = fmaf(a1.w, w1.w, v);
                sw[i] = v;
            }
        }
    }

    // --- input tile: LDG.128 + aligned STS.128 (col g at index g+4) ---
    const float* xb = x + (size_t)b * (8 * 65536);
    {
        int w5 = tx >> 5;          // 0..3
        int q  = tx & 31;          // quad 0..31
#pragma unroll
        for (int pass = 0; pass < 20; pass++) {
            int row = pass * 4 + w5;      // 0..79 = c*10 + t
            int c = row / 10;
            int t = row - c * 10;
            int gy = y0 - 1 + t;
            float4 v = make_float4(0.f, 0.f, 0.f, 0.f);
            if ((unsigned)gy < 256u)
                v = *(const float4*)(xb + c * 65536 + gy * 256 + x0 + 4 * q);
            *(float4*)(sin + row * SIN_STRIDE + 4 * q + 4) = v;
        }
        // halo: left (x0-1) -> idx 3, right (x0+128) -> idx 132
#pragma unroll
        for (int side = 0; side < 2; side++) {
            if (tx < 80) {
                int c = tx / 10;
                int t = tx - c * 10;
                int gy = y0 - 1 + t;
                int gx = side ? (x0 + 128) : (x0 - 1);
                float v = 0.f;
                if (((unsigned)gy < 256u) && ((unsigned)gx < 256u))
                    v = __ldg(xb + c * 65536 + gy * 256 + gx);
                sin[tx * SIN_STRIDE + (side ? 132 : 3)] = v;
            }
        }
    }
    __syncthreads();

    // --- accumulate: acc[r][q] packs och (2q, 2q+1) for this column ---
    u64 acc[TY][4];
#pragma unroll
    for (int r = 0; r < TY; r++)
#pragma unroll
        for (int q = 0; q < 4; q++) acc[r][q] = 0ull;

    const double2* swd = (const double2*)sw;

#pragma unroll 1
    for (int c = 0; c < 8; c++) {
        // 36 och-pairs for all 8 och: 2 broadcast LDS.128 per tap,
        // register-pair aliasing via double2 (no movs)
        u64 w[9][4];
#pragma unroll
        for (int kk = 0; kk < 9; kk++) {
            double2 A = swd[(c * 9 + kk) * 2 + 0];
            double2 B = swd[(c * 9 + kk) * 2 + 1];
            w[kk][0] = __double_as_longlong(A.x);
            w[kk][1] = __double_as_longlong(A.y);
            w[kk][2] = __double_as_longlong(B.x);
            w[kk][3] = __double_as_longlong(B.y);
        }
        const float* sc = sin + c * SIN_PER_C + tx;
#pragma unroll
        for (int t = 0; t < SIN_ROWS; t++) {
            float v0 = sc[t * SIN_STRIDE + 3];   // col cx-1
            float v1 = sc[t * SIN_STRIDE + 4];   // col cx
            float v2 = sc[t * SIN_STRIDE + 5];   // col cx+1
            u64 d0, d1, d2;                      // (v,v) splats
            asm("mov.b64 %0, {%1, %1};" : "=l"(d0) : "f"(v0));
            asm("mov.b64 %0, {%1, %1};" : "=l"(d1) : "f"(v1));
            asm("mov.b64 %0, {%1, %1};" : "=l"(d2) : "f"(v2));
#pragma unroll
            for (int kh = 0; kh < 3; kh++) {
                int r = t - kh;                  // output row this tap feeds
                if (r >= 0 && r < TY) {
#pragma unroll
                    for (int q = 0; q < 4; q++) {
                        asm("fma.rn.f32x2 %0, %1, %2, %0;"
                            : "+l"(acc[r][q]) : "l"(d0), "l"(w[kh * 3 + 0][q]));
                        asm("fma.rn.f32x2 %0, %1, %2, %0;"
                            : "+l"(acc[r][q]) : "l"(d1), "l"(w[kh * 3 + 1][q]));
                        asm("fma.rn.f32x2 %0, %1, %2, %0;"
                            : "+l"(acc[r][q]) : "l"(d2), "l"(w[kh * 3 + 2][q]));
                    }
                }
            }
        }
    }

    // --- write out: acc[r][q] = (och 2q, och 2q+1), scalar STG each ---
    float* ob = out + (size_t)b * (8 * 65536) + x0;
#pragma unroll
    for (int r = 0; r < TY; r++) {
#pragma unroll
        for (int q = 0; q < 4; q++) {
            unsigned lo, hi;
            asm("mov.b64 {%0, %1}, %2;" : "=r"(lo), "=r"(hi) : "l"(acc[r][q]));
            ob[(2 * q + 0) * 65536 + (y0 + r) * 256 + tx] = __uint_as_float(lo);
            ob[(2 * q + 1) * 65536 + (y0 + r) * 256 + tx] = __uint_as_float(hi);
        }
    }
}

extern "C" void kernel_launch(void* const* d_in, const int* in_sizes, int n_in,
                              void* d_out, int out_size) {
    const float* x  = (const float*)d_in[0];
    const float* dw = (const float*)d_in[1];
    const float* Wg = (const float*)d_in[2];
    const float* bg = (const float*)d_in[3];
    float* out = (float*)d_out;

    cudaFuncSetAttribute(conv_kernel, cudaFuncAttributeMaxDynamicSharedMemorySize,
                         SMEM_BYTES);

    conv_kernel<<<64 * 32 * 2, 128, SMEM_BYTES>>>(x, dw, Wg, bg, out);
}